// round 1
// baseline (speedup 1.0000x reference)
#include <cuda_runtime.h>
#include <math.h>

#define N      8192
#define D      64
#define DA     65          // 64 h-dims + 1 Z column
#define NB     16384       // buckets
#define ALPHA  0.2f
#define CHUNK  128
#define NCHUNK (N / CHUNK) // 64
#define RLO   (-12.0f)
#define RHI   (12.0f)

// ---------------- scratch (device globals; no allocation allowed) -------------
__device__ float g_h[N * D];
__device__ float g_f1[N];
__device__ float g_f2[N];
__device__ int   g_cnt[NB];
__device__ int   g_cur[NB];
__device__ int   g_start[NB + 1];
__device__ int   g_ord[N];
__device__ float g_f2s[N];
__device__ float g_gp[N * DA];          // e^{f2} * [h, 1]
__device__ float g_gn[N * DA];          // e^{a*f2} * [h, 1]
__device__ float g_suf[(N + 1) * DA];   // suffix sums of gp
__device__ float g_pre[(N + 1) * DA];   // prefix sums of gn
__device__ float g_csum[2][NCHUNK][DA];
__device__ float g_coff[2][NCHUNK][DA];

__device__ __forceinline__ int bucket_of(float v) {
    float t = (v - RLO) * ((float)NB / (RHI - RLO));
    int b = (int)t;               // truncation; clamp makes it consistent+monotone
    if (b < 0) b = 0;
    if (b > NB - 1) b = NB - 1;
    return b;
}

// ---------------- 0: reset per-call state ------------------------------------
__global__ void k_init() {
    int i = blockIdx.x * blockDim.x + threadIdx.x;
    int stride = gridDim.x * blockDim.x;
    for (int k = i; k < NB; k += stride) { g_cnt[k] = 0; g_cur[k] = 0; }
}

// ---------------- 1: h = x @ Wt ; f1 = h.a1 + b1 ; f2 = h.a2 + b2 ------------
__global__ void __launch_bounds__(256) k_hf(
    const float* __restrict__ x, const float* __restrict__ Wt,
    const float* __restrict__ a1, const float* __restrict__ b1,
    const float* __restrict__ a2, const float* __restrict__ b2) {
    __shared__ float sW[D * D];
    __shared__ float sx[4 * D];
    __shared__ float s1[8], s2[8];
    int tid = threadIdx.x;
    int row0 = blockIdx.x * 4;
    for (int i = tid; i < D * D; i += 256) sW[i] = Wt[i];
    for (int i = tid; i < 4 * D; i += 256) sx[i] = x[row0 * D + i];
    __syncthreads();
    int r = tid >> 6;          // 0..3 local row
    int o = tid & 63;          // output dim
    float acc = 0.0f;
#pragma unroll
    for (int i = 0; i < D; i++) acc = fmaf(sx[r * D + i], sW[i * D + o], acc);
    int row = row0 + r;
    g_h[row * D + o] = acc;

    float p1 = acc * a1[o];
    float p2 = acc * a2[o];
#pragma unroll
    for (int s = 16; s > 0; s >>= 1) {
        p1 += __shfl_xor_sync(0xffffffffu, p1, s);
        p2 += __shfl_xor_sync(0xffffffffu, p2, s);
    }
    int wp = tid >> 5;
    if ((tid & 31) == 0) { s1[wp] = p1; s2[wp] = p2; }
    __syncthreads();
    if (o == 0) {
        g_f1[row] = s1[2 * r] + s1[2 * r + 1] + b1[0];
        g_f2[row] = s2[2 * r] + s2[2 * r + 1] + b2[0];
    }
}

// ---------------- 2: bucket histogram ----------------------------------------
__global__ void k_count() {
    int j = blockIdx.x * blockDim.x + threadIdx.x;
    if (j < N) atomicAdd(&g_cnt[bucket_of(g_f2[j])], 1);
}

// ---------------- 3: exclusive scan of bucket counts (one block) -------------
__global__ void __launch_bounds__(1024) k_scan() {
    int tid = threadIdx.x;                 // 0..1023, 16 buckets each
    int base = tid * 16;
    int v[16];
    int tot = 0;
#pragma unroll
    for (int k = 0; k < 16; k++) { v[k] = g_cnt[base + k]; tot += v[k]; }
    int lane = tid & 31, wp = tid >> 5;
    int inc = tot;
#pragma unroll
    for (int s = 1; s < 32; s <<= 1) {
        int t = __shfl_up_sync(0xffffffffu, inc, s);
        if (lane >= s) inc += t;
    }
    __shared__ int ws[32];
    if (lane == 31) ws[wp] = inc;
    __syncthreads();
    if (wp == 0) {
        int t = ws[lane];
#pragma unroll
        for (int s = 1; s < 32; s <<= 1) {
            int u = __shfl_up_sync(0xffffffffu, t, s);
            if (lane >= s) t += u;
        }
        ws[lane] = t;
    }
    __syncthreads();
    int run = inc - tot + (wp > 0 ? ws[wp - 1] : 0);   // exclusive offset
#pragma unroll
    for (int k = 0; k < 16; k++) { g_start[base + k] = run; run += v[k]; }
    if (tid == 1023) g_start[NB] = run;
}

// ---------------- 4: place nodes into bucket-grouped order -------------------
__global__ void k_place() {
    int j = blockIdx.x * blockDim.x + threadIdx.x;
    if (j < N) {
        float f = g_f2[j];
        int b = bucket_of(f);
        int pos = g_start[b] + atomicAdd(&g_cur[b], 1);
        g_ord[pos] = j;
        g_f2s[pos] = f;
    }
}

// ---------------- 5: weighted vectors gp / gn --------------------------------
__global__ void __launch_bounds__(256) k_gather() {
    int tid = threadIdx.x;
    int r = blockIdx.x * 4 + (tid >> 6);
    int d = tid & 63;
    int j = g_ord[r];
    float f = g_f2s[r];
    float ep = expf(f);
    float en = expf(ALPHA * f);
    float hv = g_h[j * D + d];
    g_gp[r * DA + d] = ep * hv;
    g_gn[r * DA + d] = en * hv;
    if (d == 0) { g_gp[r * DA + 64] = ep; g_gn[r * DA + 64] = en; }
}

// ---------------- 6: per-chunk partial sums ----------------------------------
__global__ void kA() {
    int c = blockIdx.x, a = blockIdx.y, d = threadIdx.x;   // d in 0..64
    const float* __restrict__ src = a ? g_gn : g_gp;
    float s = 0.0f;
    int base = c * CHUNK;
    for (int k = 0; k < CHUNK; k++) s += src[(base + k) * DA + d];
    g_csum[a][c][d] = s;
}

// ---------------- 7: scan chunk sums (prefix for gn, suffix for gp) ----------
__global__ void kB() {
    int tid = threadIdx.x;            // 0..129
    if (tid >= 2 * DA) return;
    int a = tid / DA, d = tid % DA;
    if (a == 1) {                     // gn: prefix (ascending)
        float run = 0.0f;
        for (int c = 0; c < NCHUNK; c++) { g_coff[1][c][d] = run; run += g_csum[1][c][d]; }
    } else {                          // gp: suffix (descending)
        float run = 0.0f;
        for (int c = NCHUNK - 1; c >= 0; c--) { g_coff[0][c][d] = run; run += g_csum[0][c][d]; }
    }
}

// ---------------- 8: emit full prefix/suffix tables --------------------------
__global__ void kC() {
    int c = blockIdx.x, a = blockIdx.y, d = threadIdx.x;
    int base = c * CHUNK;
    if (a == 1) {                     // g_pre[p] = sum_{r<p} gn[r]
        float run = g_coff[1][c][d];
        for (int k = 0; k < CHUNK; k++) {
            int r = base + k;
            g_pre[r * DA + d] = run;
            run += g_gn[r * DA + d];
        }
        if (c == NCHUNK - 1) g_pre[N * DA + d] = run;
    } else {                          // g_suf[p] = sum_{r>=p} gp[r]
        float run = g_coff[0][c][d];
        for (int k = CHUNK - 1; k >= 0; k--) {
            int r = base + k;
            run += g_gp[r * DA + d];
            g_suf[r * DA + d] = run;
        }
        if (c == NCHUNK - 1) g_suf[N * DA + d] = 0.0f;
    }
}

// ---------------- 9: per-row query + ELU -------------------------------------
__global__ void __launch_bounds__(256) k_out(float* __restrict__ out) {
    int tid = threadIdx.x;
    int i = blockIdx.x * 4 + (tid >> 6);
    int d = tid & 63;
    float f1 = g_f1[i];
    float thr = -f1;
    int b = bucket_of(thr);
    int p0 = g_start[b], p1 = g_start[b + 1];
    float pos  = g_suf[p1 * DA + d];
    float neg  = g_pre[p0 * DA + d];
    float posZ = g_suf[p1 * DA + 64];
    float negZ = g_pre[p0 * DA + 64];
    for (int r = p0; r < p1; r++) {       // residual: exact split of threshold bucket
        float f = g_f2s[r];
        if (f >= thr) {
            pos  += g_gp[r * DA + d];
            posZ += g_gp[r * DA + 64];
        } else {
            neg  += g_gn[r * DA + d];
            negZ += g_gn[r * DA + 64];
        }
    }
    float w = expf((1.0f - ALPHA) * f1);
    float v = (w * pos + neg) / (w * posZ + negZ);
    out[i * D + d] = (v > 0.0f) ? v : expm1f(v);
}

// ---------------- launch ------------------------------------------------------
extern "C" void kernel_launch(void* const* d_in, const int* in_sizes, int n_in,
                              void* d_out, int out_size) {
    const float* x  = (const float*)d_in[0];
    const float* Wt = (const float*)d_in[1];
    const float* a1 = (const float*)d_in[2];
    const float* b1 = (const float*)d_in[3];
    const float* a2 = (const float*)d_in[4];
    const float* b2 = (const float*)d_in[5];
    float* out = (float*)d_out;

    k_init<<<64, 256>>>();
    k_hf<<<N / 4, 256>>>(x, Wt, a1, b1, a2, b2);
    k_count<<<N / 256, 256>>>();
    k_scan<<<1, 1024>>>();
    k_place<<<N / 256, 256>>>();
    k_gather<<<N / 4, 256>>>();
    kA<<<dim3(NCHUNK, 2), DA>>>();
    kB<<<1, 2 * DA>>>();
    kC<<<dim3(NCHUNK, 2), DA>>>();
    k_out<<<N / 4, 256>>>(out);
}

// round 2
// speedup vs baseline: 2.0685x; 2.0685x over previous
#include <cuda_runtime.h>
#include <math.h>

#define N      8192
#define D      64
#define DA     65          // 64 h-dims + 1 Z column
#define NB     4096        // buckets
#define ALPHA  0.2f
#define RPB    16          // rows per block in k_hf
#define RLO   (-10.0f)
#define RHI   (10.0f)

// ---------------- scratch (device globals; no allocation allowed) -------------
__device__ float g_h[N * D];
__device__ float g_f1[N];
__device__ float g_f2[N];
__device__ int   g_cnt[NB];
__device__ int   g_start[NB + 1];
__device__ int   g_ord[N];
__device__ float g_f2s[N];
__device__ float g_accP[NB * DA];        // per-bucket sums of e^{f2} * [h, 1]
__device__ float g_accN[NB * DA];        // per-bucket sums of e^{a f2} * [h, 1]
__device__ float g_tp[(NB + 1) * DA];    // suffix sums of accP over buckets
__device__ float g_tn[NB * DA];          // exclusive prefix sums of accN over buckets

__device__ __forceinline__ int bucket_of(float v) {
    float t = (v - RLO) * ((float)NB / (RHI - RLO));
    int b = (int)t;               // truncation; monotone non-decreasing in v
    if (b < 0) b = 0;
    if (b > NB - 1) b = NB - 1;
    return b;
}

// ---------------- 0: reset per-call state ------------------------------------
__global__ void k_init() {
    int i = blockIdx.x * blockDim.x + threadIdx.x;
    int stride = gridDim.x * blockDim.x;
    for (int k = i; k < NB; k += stride) g_cnt[k] = 0;
    for (int k = i; k < NB * DA; k += stride) { g_accP[k] = 0.0f; g_accN[k] = 0.0f; }
}

// ------- 1: h = x @ Wt ; f1,f2 ; histogram ; bucket-level gp/gn accumulation --
__global__ void __launch_bounds__(256) k_hf(
    const float* __restrict__ x, const float* __restrict__ Wt,
    const float* __restrict__ a1, const float* __restrict__ b1,
    const float* __restrict__ a2, const float* __restrict__ b2) {
    __shared__ float sW[D * D];          // 16KB
    __shared__ float sx[RPB * D];        // 4KB
    __shared__ float sp1[8][4], sp2[8][4];
    __shared__ float sf2[RPB];
    int tid = threadIdx.x;
    int row0 = blockIdx.x * RPB;
    for (int i = tid; i < D * D; i += 256) sW[i] = Wt[i];
    for (int i = tid; i < RPB * D; i += 256) sx[i] = x[row0 * D + i];
    __syncthreads();

    int o  = tid & 63;                   // output dim
    int rg = tid >> 6;                   // 0..3, rows rg*4 + q
    float acc[4] = {0.f, 0.f, 0.f, 0.f};
#pragma unroll
    for (int i = 0; i < D; i++) {
        float wv = sW[i * D + o];
#pragma unroll
        for (int q = 0; q < 4; q++) acc[q] = fmaf(sx[(rg * 4 + q) * D + i], wv, acc[q]);
    }
#pragma unroll
    for (int q = 0; q < 4; q++) g_h[(row0 + rg * 4 + q) * D + o] = acc[q];

    float A1 = a1[o], A2 = a2[o];
    float p1[4], p2[4];
#pragma unroll
    for (int q = 0; q < 4; q++) { p1[q] = acc[q] * A1; p2[q] = acc[q] * A2; }
#pragma unroll
    for (int s = 16; s > 0; s >>= 1) {
#pragma unroll
        for (int q = 0; q < 4; q++) {
            p1[q] += __shfl_xor_sync(0xffffffffu, p1[q], s);
            p2[q] += __shfl_xor_sync(0xffffffffu, p2[q], s);
        }
    }
    int lane = tid & 31, w = tid >> 5;
    if (lane == 0) {
#pragma unroll
        for (int q = 0; q < 4; q++) { sp1[w][q] = p1[q]; sp2[w][q] = p2[q]; }
    }
    __syncthreads();
    if (tid < RPB) {                     // tid = rg*4+q → row row0+tid
        int wb = (tid >> 2) * 2, q = tid & 3;
        float f1v = sp1[wb][q] + sp1[wb + 1][q] + b1[0];
        float f2v = sp2[wb][q] + sp2[wb + 1][q] + b2[0];
        g_f1[row0 + tid] = f1v;
        g_f2[row0 + tid] = f2v;
        sf2[tid] = f2v;
    }
    __syncthreads();
#pragma unroll
    for (int q = 0; q < 4; q++) {
        float f2v = sf2[rg * 4 + q];
        float ep = expf(f2v);
        float en = expf(ALPHA * f2v);
        int b = bucket_of(f2v);
        atomicAdd(&g_accP[b * DA + o], ep * acc[q]);
        atomicAdd(&g_accN[b * DA + o], en * acc[q]);
        if (o == 0) {
            atomicAdd(&g_accP[b * DA + 64], ep);
            atomicAdd(&g_accN[b * DA + 64], en);
            atomicAdd(&g_cnt[b], 1);
        }
    }
}

// ------- 2: single-block scan of bucket counts + counting-sort placement -----
__global__ void __launch_bounds__(1024) k_scanplace() {
    __shared__ int sstart[NB + 1];
    __shared__ int scur[NB];
    __shared__ int wsum[32];
    int t = threadIdx.x;
    int4 c4 = *(const int4*)&g_cnt[t * 4];
    int v[4] = {c4.x, c4.y, c4.z, c4.w};
    int tot = v[0] + v[1] + v[2] + v[3];
    int lane = t & 31, w = t >> 5;
    int inc = tot;
#pragma unroll
    for (int s = 1; s < 32; s <<= 1) {
        int tv = __shfl_up_sync(0xffffffffu, inc, s);
        if (lane >= s) inc += tv;
    }
    if (lane == 31) wsum[w] = inc;
    __syncthreads();
    if (w == 0) {
        int u = wsum[lane];
#pragma unroll
        for (int s = 1; s < 32; s <<= 1) {
            int tv = __shfl_up_sync(0xffffffffu, u, s);
            if (lane >= s) u += tv;
        }
        wsum[lane] = u;
    }
    __syncthreads();
    int run = inc - tot + (w > 0 ? wsum[w - 1] : 0);
#pragma unroll
    for (int k = 0; k < 4; k++) {
        int b = t * 4 + k;
        sstart[b] = run;
        g_start[b] = run;
        scur[b] = 0;
        run += v[k];
    }
    if (t == 1023) { sstart[NB] = run; g_start[NB] = run; }
    __syncthreads();
    // placement: counting sort of node ids by bucket
#pragma unroll
    for (int k = 0; k < N / 1024; k++) {
        int j = k * 1024 + t;
        float f = g_f2[j];
        int b = bucket_of(f);
        int pos = sstart[b] + atomicAdd(&scur[b], 1);
        g_ord[pos] = j;
        g_f2s[pos] = f;
    }
}

// ------- 3: bucket-level suffix (accP) / exclusive-prefix (accN) tables ------
// One block per (pass, dim): block-scan over NB=4096 buckets (256 thr x 16).
__global__ void __launch_bounds__(256) k_tables() {
    int bx = blockIdx.x;                  // 0 .. 2*DA-1
    int a = bx / DA;                      // 0: accP suffix, 1: accN prefix
    int d = bx % DA;
    int t = threadIdx.x;
    const float* __restrict__ acc = a ? g_accN : g_accP;
    float vals[16];
    float run = 0.0f;
#pragma unroll
    for (int k = 0; k < 16; k++) {
        int r = t * 16 + k;
        int b = a ? r : (NB - 1 - r);
        vals[k] = acc[b * DA + d];
        run += vals[k];
    }
    int lane = t & 31, w = t >> 5;
    float inc = run;
#pragma unroll
    for (int s = 1; s < 32; s <<= 1) {
        float tv = __shfl_up_sync(0xffffffffu, inc, s);
        if (lane >= s) inc += tv;
    }
    __shared__ float ws[8];
    if (lane == 31) ws[w] = inc;
    __syncthreads();
    if (w == 0 && lane < 8) {
        float u = ws[lane];
#pragma unroll
        for (int s = 1; s < 8; s <<= 1) {
            float tv = __shfl_up_sync(0x000000ffu, u, s);
            if (lane >= s) u += tv;
        }
        ws[lane] = u;
    }
    __syncthreads();
    float base = (inc - run) + (w > 0 ? ws[w - 1] : 0.0f);
    float run2 = base;
#pragma unroll
    for (int k = 0; k < 16; k++) {
        int r = t * 16 + k;
        if (a) {                          // exclusive prefix: tn[b] = sum_{b'<b}
            g_tn[r * DA + d] = run2;
        } else {                          // inclusive suffix: tp[b] = sum_{b'>=b}
            int b = NB - 1 - r;
            g_tp[b * DA + d] = run2 + vals[k];
        }
        run2 += vals[k];
    }
    if (a == 0 && t == 0) g_tp[NB * DA + d] = 0.0f;   // sentinel
}

// ---------------- 4: per-row query + residual + ELU --------------------------
__global__ void __launch_bounds__(256) k_out(float* __restrict__ out) {
    int tid = threadIdx.x;
    int i = blockIdx.x * 4 + (tid >> 6);
    int d = tid & 63;
    float f1 = g_f1[i];
    float thr = -f1;
    int b = bucket_of(thr);
    float pos  = g_tp[(b + 1) * DA + d];
    float posZ = g_tp[(b + 1) * DA + 64];
    float neg  = g_tn[b * DA + d];
    float negZ = g_tn[b * DA + 64];
    int p0 = g_start[b], p1 = g_start[b + 1];
    for (int p = p0; p < p1; p++) {       // exact split of threshold bucket
        float f = g_f2s[p];
        int j = g_ord[p];
        float hv = g_h[j * D + d];
        if (f >= thr) {
            float e = expf(f);
            pos  += e * hv;
            posZ += e;
        } else {
            float e = expf(ALPHA * f);
            neg  += e * hv;
            negZ += e;
        }
    }
    float w = expf((1.0f - ALPHA) * f1);
    float v = (w * pos + neg) / (w * posZ + negZ);
    out[i * D + d] = (v > 0.0f) ? v : expm1f(v);
}

// ---------------- launch ------------------------------------------------------
extern "C" void kernel_launch(void* const* d_in, const int* in_sizes, int n_in,
                              void* d_out, int out_size) {
    const float* x  = (const float*)d_in[0];
    const float* Wt = (const float*)d_in[1];
    const float* a1 = (const float*)d_in[2];
    const float* b1 = (const float*)d_in[3];
    const float* a2 = (const float*)d_in[4];
    const float* b2 = (const float*)d_in[5];
    float* out = (float*)d_out;

    k_init<<<256, 256>>>();
    k_hf<<<N / RPB, 256>>>(x, Wt, a1, b1, a2, b2);
    k_scanplace<<<1, 1024>>>();
    k_tables<<<2 * DA, 256>>>();
    k_out<<<N / 4, 256>>>(out);
}